// round 8
// baseline (speedup 1.0000x reference)
#include <cuda_runtime.h>
#include <cuda_bf16.h>

// STFT: B=16, T=262144, n_fft=2048, hop=512, center reflect pad 1024.
// n_frames = 513, n_bins = 1025. Output [real(16,1025,513); imag(...)] fp32.
//
// 8 frames/CTA (512 thr, 64 thr/frame). 1024-pt complex FFT (real packing),
// Stockham radices 8,8,16. Stage 1 reads gmem; stage 3 (radix-16, twiddle-free)
// runs fully in registers; rfft unpack via warp shuffle (conjugate classes
// mapped to lanes l ^ 16); X written once to smem; full-sector transposed store.

#define NC        1024
#define SROW      1026
#define HOP       512
#define PADC      1024
#define T_LEN     262144
#define NFFT      2048
#define NFRAMES   513
#define NBINS     1025
#define NB        16
#define THREADS   512
#define FPB       8
#define NGRP      65
#define PI_F      3.14159265358979323846f
#define C4        0.70710678118654752f
// W16^1 = exp(-i*pi/8): cos(pi/8), sin(pi/8)
#define C16_1     0.92387953251129f
#define S16_1     0.38268343236509f

#define PHY(i) ((i) ^ ((((unsigned)(i)) >> 3) & 15u))

__device__ __forceinline__ float2 cadd(float2 a, float2 b) { return make_float2(a.x + b.x, a.y + b.y); }
__device__ __forceinline__ float2 csub(float2 a, float2 b) { return make_float2(a.x - b.x, a.y - b.y); }
__device__ __forceinline__ float2 cmulc(float2 a, float2 w) {
    return make_float2(a.x * w.x - a.y * w.y, a.x * w.y + a.y * w.x);
}
// a * (c - i s)
__device__ __forceinline__ float2 cmK(float2 a, float c, float s) {
    return make_float2(a.x * c + a.y * s, a.y * c - a.x * s);
}

__device__ __forceinline__ void fft8(float2* a) {
    float2 e0 = cadd(a[0], a[4]), e1 = cadd(a[1], a[5]);
    float2 e2 = cadd(a[2], a[6]), e3 = cadd(a[3], a[7]);
    float2 o0 = csub(a[0], a[4]), o1 = csub(a[1], a[5]);
    float2 o2 = csub(a[2], a[6]), o3 = csub(a[3], a[7]);
    float2 ee0 = cadd(e0, e2), ee1 = cadd(e1, e3);
    float2 eo0 = csub(e0, e2), eo1 = csub(e1, e3);
    a[0] = cadd(ee0, ee1);
    a[4] = csub(ee0, ee1);
    a[2] = make_float2(eo0.x + eo1.y, eo0.y - eo1.x);
    a[6] = make_float2(eo0.x - eo1.y, eo0.y + eo1.x);
    float2 p1 = make_float2(C4 * (o1.x + o1.y), C4 * (o1.y - o1.x));
    float2 p2 = make_float2(o2.y, -o2.x);
    float2 p3 = make_float2(C4 * (o3.y - o3.x), -C4 * (o3.x + o3.y));
    float2 s0 = cadd(o0, p2), s1 = cadd(p1, p3);
    float2 d0 = csub(o0, p2), d1 = csub(p1, p3);
    a[1] = cadd(s0, s1);
    a[5] = csub(s0, s1);
    a[3] = make_float2(d0.x + d1.y, d0.y - d1.x);
    a[7] = make_float2(d0.x - d1.y, d0.y + d1.x);
}

__device__ __forceinline__ void fft4(float2& a0, float2& a1, float2& a2, float2& a3) {
    float2 t0 = cadd(a0, a2), t1 = csub(a0, a2);
    float2 t2 = cadd(a1, a3), t3 = csub(a1, a3);
    a0 = cadd(t0, t2);
    a2 = csub(t0, t2);
    float2 b1 = make_float2(t1.x + t3.y, t1.y - t3.x);
    float2 b3 = make_float2(t1.x - t3.y, t1.y + t3.x);
    a1 = b1;
    a3 = b3;
}

// natural-order 16-pt DFT in registers: out[k] = sum_q in[q] * W16^(kq)
__device__ __forceinline__ void fft16(float2* a) {
    float2 b[16];
#pragma unroll
    for (int j = 0; j < 4; j++) {
        float2 y0 = a[j], y1 = a[j + 4], y2 = a[j + 8], y3 = a[j + 12];
        fft4(y0, y1, y2, y3);
        if (j == 1) {                       // W16^{1,2,3}
            y1 = cmK(y1, C16_1, S16_1);
            y2 = cmK(y2, C4, C4);
            y3 = cmK(y3, S16_1, C16_1);
        } else if (j == 2) {                // W16^{2,4,6}
            y1 = cmK(y1, C4, C4);
            y2 = make_float2(y2.y, -y2.x);  // *(-i)
            y3 = cmK(y3, -C4, C4);
        } else if (j == 3) {                // W16^{3,6,9}
            y1 = cmK(y1, S16_1, C16_1);
            y2 = cmK(y2, -C4, C4);
            y3 = cmK(y3, -C16_1, -S16_1);
        }
        b[4 * j] = y0; b[4 * j + 1] = y1; b[4 * j + 2] = y2; b[4 * j + 3] = y3;
    }
#pragma unroll
    for (int j = 0; j < 4; j++) {
        float2 y0 = b[j], y1 = b[j + 4], y2 = b[j + 8], y3 = b[j + 12];
        fft4(y0, y1, y2, y3);
        a[j] = y0; a[j + 4] = y1; a[j + 8] = y2; a[j + 12] = y3;
    }
}

__device__ __forceinline__ void bar_frame(int fl) {
    asm volatile("bar.sync %0, 64;" :: "r"(fl + 1) : "memory");
}

extern __shared__ float2 buf[];   // FPB * SROW float2 = 65,664 B

__global__ __launch_bounds__(THREADS, 2)
void stft_kernel(const float* __restrict__ x,
                 const float* __restrict__ win,
                 float* __restrict__ out) {
    const int g   = blockIdx.x % NGRP;
    const int b   = blockIdx.x / NGRP;
    const int tid = threadIdx.x;
    const int fl  = tid >> 6;
    const int u   = tid & 63;
    const int f   = g * FPB + fl;
    const float* __restrict__ xb = x + (long)b * T_LEN;
    const int base = f * HOP - PADC;
    float2* __restrict__ row = buf + fl * SROW;

    // ---- stage 1: radix-8, n=1024, s=1 — read gmem directly ----
    const bool interior = (base >= 0) && (base + NFFT <= T_LEN);
#pragma unroll
    for (int h = 0; h < 2; h++) {
        const int t = u + (h << 6);
        float2 a[8];
        if (interior) {
            const float2* __restrict__ xv = (const float2*)(xb + base);
            const float2* __restrict__ wv = (const float2*)win;
#pragma unroll
            for (int r = 0; r < 8; r++) {
                const int n = t + (r << 7);
                const float2 v = xv[n];
                const float2 w = wv[n];
                a[r] = make_float2(v.x * w.x, v.y * w.y);
            }
        } else {
#pragma unroll
            for (int r = 0; r < 8; r++) {
                const int n = t + (r << 7);
                int t0 = base + 2 * n;
                int t1 = base + 2 * n + 1;
                t0 = (t0 < 0) ? -t0 : ((t0 >= T_LEN) ? 2 * T_LEN - 2 - t0 : t0);
                t1 = (t1 < 0) ? -t1 : ((t1 >= T_LEN) ? 2 * T_LEN - 2 - t1 : t1);
                a[r] = make_float2(xb[t0] * win[2 * n], xb[t1] * win[2 * n + 1]);
            }
        }
        fft8(a);
        float s1, c1;
        __sincosf((float)t * (-2.0f * PI_F / 1024.0f), &s1, &c1);
        const float2 w1 = make_float2(c1, s1);
        float2 wk = w1;
        a[1] = cmulc(a[1], wk);
#pragma unroll
        for (int r = 2; r < 8; r++) { wk = cmulc(wk, w1); a[r] = cmulc(a[r], wk); }
#pragma unroll
        for (int r = 0; r < 8; r++) row[PHY(8 * t + r)] = a[r];
    }
    bar_frame(fl);

    // ---- stage 2: radix-8, n=128, s=8 ----
    {
        float2 A[2][8];
#pragma unroll
        for (int h = 0; h < 2; h++) {
            const int t = u + (h << 6);
#pragma unroll
            for (int r = 0; r < 8; r++) A[h][r] = row[PHY(t + (r << 7))];
        }
        bar_frame(fl);
#pragma unroll
        for (int h = 0; h < 2; h++) {
            const int t = u + (h << 6);
            fft8(A[h]);
            const int p = t >> 3;
            float s1, c1;
            __sincosf((float)p * (-2.0f * PI_F / 128.0f), &s1, &c1);
            const float2 w1 = make_float2(c1, s1);
            float2 wk = w1;
            A[h][1] = cmulc(A[h][1], wk);
#pragma unroll
            for (int r = 2; r < 8; r++) { wk = cmulc(wk, w1); A[h][r] = cmulc(A[h][r], wk); }
            const int dbase = t + 56 * p;
#pragma unroll
            for (int r = 0; r < 8; r++) row[PHY(dbase + 8 * r)] = A[h][r];
        }
        bar_frame(fl);
    }

    // ---- stage 3: radix-16 (n=16, s=64, p=0 -> twiddle-free), in registers ----
    // Thread column c chosen so conjugate classes (c, 64-c) are lanes l ^ 16.
    const int l = u & 31;
    const int w16 = (u >> 5) << 4;        // 0 or 16
    int c;
    if (l < 15)       c = l + 1 + w16;    // w0: 1..15   w1: 17..31
    else if (l == 15) c = w16;            // w0: 0       w1: 16
    else if (l < 31)  c = 79 - l - w16;   // w0: 63..49  w1: 47..33
    else              c = 32 + w16;       // w0: 32      w1: 48

    float2 Z[16];
#pragma unroll
    for (int r = 0; r < 16; r++) Z[r] = row[PHY(c + (r << 6))];
    bar_frame(fl);     // all frame reads done before X overwrites buf
    fft16(Z);          // Z[r] = full FFT bin (c + 64r)

    // ---- rfft unpack via shuffle; write X[k] to smem ----
    {
        // theta_k = pi*c/1024 + r*pi/16
        const float CT[16] = { 1.0f, 0.98078528f, 0.92387953f, 0.83146961f,
                               0.70710678f, 0.55557023f, 0.38268343f, 0.19509032f,
                               0.0f, -0.19509032f, -0.38268343f, -0.55557023f,
                              -0.70710678f, -0.83146961f, -0.92387953f, -0.98078528f };
        const float ST[16] = { 0.0f, 0.19509032f, 0.38268343f, 0.55557023f,
                               0.70710678f, 0.83146961f, 0.92387953f, 0.98078528f,
                               1.0f, 0.98078528f, 0.92387953f, 0.83146961f,
                               0.70710678f, 0.55557023f, 0.38268343f, 0.19509032f };
        float ca, sa;
        __sincosf((float)c * (PI_F / 1024.0f), &sa, &ca);
#pragma unroll
        for (int r = 0; r < 16; r++) {
            const float2 zk = Z[r];
            const float px = __shfl_xor_sync(0xffffffffu, Z[15 - r].x, 16);
            const float py = __shfl_xor_sync(0xffffffffu, Z[15 - r].y, 16);
            float2 zn;
            if (c == 0)       zn = Z[(16 - r) & 15];
            else if (c == 32) zn = Z[15 - r];
            else              zn = make_float2(px, py);
            const float cw = ca * CT[r] - sa * ST[r];
            const float sw = sa * CT[r] + ca * ST[r];
            const float er  = 0.5f * (zk.x + zn.x);
            const float ei  = 0.5f * (zk.y - zn.y);
            const float orr = 0.5f * (zk.y + zn.y);
            const float oi  = 0.5f * (zn.x - zk.x);
            const float pr  = orr * cw + oi * sw;
            const float pi2 = orr * sw - oi * cw;
            row[PHY(c + (r << 6))] = make_float2(er + pr, ei - pi2);
        }
        if (c == 0)   // Nyquist bin X[1024] = Z[0].x - Z[0].y
            row[PHY(1024)] = make_float2(Z[0].x - Z[0].y, 0.0f);
    }
    __syncthreads();

    // ---- transposed store: lane j -> frame j&7, bin j>>3 (+64/iter) ----
    const int  fs     = tid & 7;
    const int  kb     = tid >> 3;
    const int  fstore = g * FPB + fs;
    const bool valid  = (fstore < NFRAMES);
    const long ro       = ((long)b * NBINS) * NFRAMES + fstore;
    const long imag_off = (long)NB * NBINS * NFRAMES;
    const float2* __restrict__ Xrow = buf + fs * SROW;
#pragma unroll
    for (int i = 0; i < 17; i++) {
        const int k = kb + (i << 6);
        if (k <= NC && valid) {
            const float2 X = Xrow[PHY(k)];
            const long o = ro + (long)k * NFRAMES;
            out[o]            = X.x;
            out[imag_off + o] = X.y;
        }
    }
}

extern "C" void kernel_launch(void* const* d_in, const int* in_sizes, int n_in,
                              void* d_out, int out_size) {
    const float* x   = (const float*)d_in[0];
    const float* win = (const float*)d_in[1];
    float* out = (float*)d_out;
    const int smem_bytes = FPB * SROW * (int)sizeof(float2);
    cudaFuncSetAttribute(stft_kernel, cudaFuncAttributeMaxDynamicSharedMemorySize,
                         smem_bytes);
    stft_kernel<<<NB * NGRP, THREADS, smem_bytes>>>(x, win, out);
}

// round 9
// speedup vs baseline: 1.0491x; 1.0491x over previous
#include <cuda_runtime.h>
#include <cuda_bf16.h>

// STFT: B=16, T=262144, n_fft=2048, hop=512, center reflect pad 1024.
// n_frames = 513, n_bins = 1025. Output [real(16,1025,513); imag(...)] fp32.
//
// 8 frames/CTA (512 thr, 64 thr/frame). 1024-pt complex FFT (real packing),
// Stockham radices 8,8,4,4; stage 1 reads gmem; stage 4 fused with rfft
// unpack; X written once to smem; full-sector transposed store.
// Twiddles via power tree (depth 3); sincosf hoisted above loads.

#define NC        1024
#define SROW      1026      // float2 row stride: 2*SROW == 4 (mod 32) banks
#define HOP       512
#define PADC      1024
#define T_LEN     262144
#define NFFT      2048
#define NFRAMES   513
#define NBINS     1025
#define NB        16
#define THREADS   512
#define FPB       8
#define NGRP      65
#define PI_F      3.14159265358979323846f
#define C4        0.70710678118654752f

#define PHY(i) ((i) ^ ((((unsigned)(i)) >> 3) & 15u))

__device__ __forceinline__ float2 cadd(float2 a, float2 b) { return make_float2(a.x + b.x, a.y + b.y); }
__device__ __forceinline__ float2 csub(float2 a, float2 b) { return make_float2(a.x - b.x, a.y - b.y); }
__device__ __forceinline__ float2 cmulc(float2 a, float2 w) {
    return make_float2(a.x * w.x - a.y * w.y, a.x * w.y + a.y * w.x);
}

__device__ __forceinline__ void fft8(float2* a) {
    float2 e0 = cadd(a[0], a[4]), e1 = cadd(a[1], a[5]);
    float2 e2 = cadd(a[2], a[6]), e3 = cadd(a[3], a[7]);
    float2 o0 = csub(a[0], a[4]), o1 = csub(a[1], a[5]);
    float2 o2 = csub(a[2], a[6]), o3 = csub(a[3], a[7]);
    float2 ee0 = cadd(e0, e2), ee1 = cadd(e1, e3);
    float2 eo0 = csub(e0, e2), eo1 = csub(e1, e3);
    a[0] = cadd(ee0, ee1);
    a[4] = csub(ee0, ee1);
    a[2] = make_float2(eo0.x + eo1.y, eo0.y - eo1.x);
    a[6] = make_float2(eo0.x - eo1.y, eo0.y + eo1.x);
    float2 p1 = make_float2(C4 * (o1.x + o1.y), C4 * (o1.y - o1.x));
    float2 p2 = make_float2(o2.y, -o2.x);
    float2 p3 = make_float2(C4 * (o3.y - o3.x), -C4 * (o3.x + o3.y));
    float2 s0 = cadd(o0, p2), s1 = cadd(p1, p3);
    float2 d0 = csub(o0, p2), d1 = csub(p1, p3);
    a[1] = cadd(s0, s1);
    a[5] = csub(s0, s1);
    a[3] = make_float2(d0.x + d1.y, d0.y - d1.x);
    a[7] = make_float2(d0.x - d1.y, d0.y + d1.x);
}

__device__ __forceinline__ void fft4(float2& a0, float2& a1, float2& a2, float2& a3) {
    float2 t0 = cadd(a0, a2), t1 = csub(a0, a2);
    float2 t2 = cadd(a1, a3), t3 = csub(a1, a3);
    a0 = cadd(t0, t2);
    a2 = csub(t0, t2);
    float2 b1 = make_float2(t1.x + t3.y, t1.y - t3.x);
    float2 b3 = make_float2(t1.x - t3.y, t1.y + t3.x);
    a1 = b1;
    a3 = b3;
}

// w^2..w^7 from w via a depth-3 multiply tree; apply to a[1..7]
__device__ __forceinline__ void twiddle8(float2* a, float2 w1) {
    const float2 w2 = cmulc(w1, w1);
    const float2 w3 = cmulc(w1, w2);
    const float2 w4 = cmulc(w2, w2);
    const float2 w5 = cmulc(w2, w3);
    const float2 w6 = cmulc(w3, w3);
    const float2 w7 = cmulc(w3, w4);
    a[1] = cmulc(a[1], w1);
    a[2] = cmulc(a[2], w2);
    a[3] = cmulc(a[3], w3);
    a[4] = cmulc(a[4], w4);
    a[5] = cmulc(a[5], w5);
    a[6] = cmulc(a[6], w6);
    a[7] = cmulc(a[7], w7);
}

__device__ __forceinline__ void bar_frame(int fl) {
    asm volatile("bar.sync %0, 64;" :: "r"(fl + 1) : "memory");
}

__device__ __forceinline__ void unpack_pair(float2 zk, float2 zn, float cw, float sw,
                                            float2& Xk, float2& Xc) {
    const float er  = 0.5f * (zk.x + zn.x);
    const float ei  = 0.5f * (zk.y - zn.y);
    const float orr = 0.5f * (zk.y + zn.y);
    const float oi  = 0.5f * (zn.x - zk.x);
    const float pr  = orr * cw + oi * sw;
    const float pi2 = orr * sw - oi * cw;
    Xk = make_float2(er + pr,  ei - pi2);
    Xc = make_float2(er - pr, -ei - pi2);
}

extern __shared__ float2 buf[];   // FPB * SROW float2 = 65,664 B

__global__ __launch_bounds__(THREADS, 2)
void stft_kernel(const float* __restrict__ x,
                 const float* __restrict__ win,
                 float* __restrict__ out) {
    const int g   = blockIdx.x % NGRP;
    const int b   = blockIdx.x / NGRP;
    const int tid = threadIdx.x;
    const int fl  = tid >> 6;
    const int u   = tid & 63;
    const int f   = g * FPB + fl;
    const float* __restrict__ xb = x + (long)b * T_LEN;
    const int base = f * HOP - PADC;
    float2* __restrict__ row = buf + fl * SROW;

    // ---- stage 1: radix-8, n=1024, s=1 — read gmem directly ----
    // hoist both twiddle roots: overlap MUFU with LDG latency
    float2 W1[2];
#pragma unroll
    for (int h = 0; h < 2; h++) {
        float s1, c1;
        __sincosf((float)(u + (h << 6)) * (-2.0f * PI_F / 1024.0f), &s1, &c1);
        W1[h] = make_float2(c1, s1);
    }
    const bool interior = (base >= 0) && (base + NFFT <= T_LEN);
#pragma unroll
    for (int h = 0; h < 2; h++) {
        const int t = u + (h << 6);
        float2 a[8];
        if (interior) {
            const float2* __restrict__ xv = (const float2*)(xb + base);
            const float2* __restrict__ wv = (const float2*)win;
#pragma unroll
            for (int r = 0; r < 8; r++) {
                const int n = t + (r << 7);
                const float2 v = xv[n];
                const float2 w = wv[n];
                a[r] = make_float2(v.x * w.x, v.y * w.y);
            }
        } else {
#pragma unroll
            for (int r = 0; r < 8; r++) {
                const int n = t + (r << 7);
                int t0 = base + 2 * n;
                int t1 = base + 2 * n + 1;
                t0 = (t0 < 0) ? -t0 : ((t0 >= T_LEN) ? 2 * T_LEN - 2 - t0 : t0);
                t1 = (t1 < 0) ? -t1 : ((t1 >= T_LEN) ? 2 * T_LEN - 2 - t1 : t1);
                a[r] = make_float2(xb[t0] * win[2 * n], xb[t1] * win[2 * n + 1]);
            }
        }
        fft8(a);
        twiddle8(a, W1[h]);
#pragma unroll
        for (int r = 0; r < 8; r++) row[PHY(8 * t + r)] = a[r];
    }
    bar_frame(fl);

    // ---- stage 2: radix-8, n=128, s=8 ----
    {
        // hoist twiddle roots (depend only on u) above the strided loads
        float2 W2[2];
#pragma unroll
        for (int h = 0; h < 2; h++) {
            const int p = (u + (h << 6)) >> 3;
            float s1, c1;
            __sincosf((float)p * (-2.0f * PI_F / 128.0f), &s1, &c1);
            W2[h] = make_float2(c1, s1);
        }
        float2 A[2][8];
#pragma unroll
        for (int h = 0; h < 2; h++) {
            const int t = u + (h << 6);
#pragma unroll
            for (int r = 0; r < 8; r++) A[h][r] = row[PHY(t + (r << 7))];
        }
        bar_frame(fl);
#pragma unroll
        for (int h = 0; h < 2; h++) {
            const int t = u + (h << 6);
            fft8(A[h]);
            twiddle8(A[h], W2[h]);
            const int dbase = t + 56 * (t >> 3);
#pragma unroll
            for (int r = 0; r < 8; r++) row[PHY(dbase + 8 * r)] = A[h][r];
        }
        bar_frame(fl);
    }

    // ---- stage 3: radix-4 x4, n=16, s=64 ----
    {
        float2 W3[4];
#pragma unroll
        for (int h = 0; h < 4; h++) {
            const int p = (u + (h << 6)) >> 6;   // == h
            float s1, c1;
            __sincosf((float)p * (-2.0f * PI_F / 16.0f), &s1, &c1);
            W3[h] = make_float2(c1, s1);
        }
        float2 A4[4][4];
#pragma unroll
        for (int h = 0; h < 4; h++) {
            const int t = u + (h << 6);
#pragma unroll
            for (int r = 0; r < 4; r++) A4[h][r] = row[PHY(t + (r << 8))];
        }
        bar_frame(fl);
#pragma unroll
        for (int h = 0; h < 4; h++) {
            const int t = u + (h << 6);
            fft4(A4[h][0], A4[h][1], A4[h][2], A4[h][3]);
            const float2 w1 = W3[h];
            const float2 w2 = cmulc(w1, w1);
            const float2 w3 = cmulc(w1, w2);
            const int dbase = t + 192 * (t >> 6);
            row[PHY(dbase)]       = A4[h][0];
            row[PHY(dbase + 64)]  = cmulc(A4[h][1], w1);
            row[PHY(dbase + 128)] = cmulc(A4[h][2], w2);
            row[PHY(dbase + 192)] = cmulc(A4[h][3], w3);
        }
        bar_frame(fl);
    }

    // ---- stage 4 (radix-4, trivial twiddles) fused with rfft unpack ----
    {
        // hoist unpack angle (depends only on u)
        float ca, sa;
        __sincosf((float)u * (PI_F / 1024.0f), &sa, &ca);

        float2 Z1[2][4], Z2[2][4];
#pragma unroll
        for (int h = 0; h < 2; h++) {
            const int ue = u + (h << 6);
            const int t1 = ue;
            const int t2 = (ue == 0) ? 128 : 256 - ue;
#pragma unroll
            for (int r = 0; r < 4; r++) {
                Z1[h][r] = row[PHY(t1 + (r << 8))];
                Z2[h][r] = row[PHY(t2 + (r << 8))];
            }
        }
        bar_frame(fl);   // all reads done before X overwrites buf
#pragma unroll
        for (int h = 0; h < 2; h++) {
            const int ue = u + (h << 6);
            fft4(Z1[h][0], Z1[h][1], Z1[h][2], Z1[h][3]);
            fft4(Z2[h][0], Z2[h][1], Z2[h][2], Z2[h][3]);
            if (ue == 0) {
                row[0]    = make_float2(Z1[h][0].x + Z1[h][0].y, 0.0f);
                row[1024] = make_float2(Z1[h][0].x - Z1[h][0].y, 0.0f);
                row[512]  = make_float2(Z1[h][2].x, -Z1[h][2].y);
                float2 Xk, Xc;
                unpack_pair(Z1[h][1], Z1[h][3], C4, C4, Xk, Xc);
                row[256] = Xk; row[768] = Xc;
                unpack_pair(Z2[h][0], Z2[h][3], 0.92387953f, 0.38268343f, Xk, Xc);
                row[128] = Xk; row[896] = Xc;
                unpack_pair(Z2[h][1], Z2[h][2], 0.38268343f, 0.92387953f, Xk, Xc);
                row[384] = Xk; row[640] = Xc;
            } else {
                // h=0: theta = a;            h=1: theta = pi/8 + a (u+64 step)
                float cb, sb;
                if (h == 0) { cb = ca; sb = sa; }
                else {
                    cb = 0.98078528f * ca - 0.19509032f * sa;
                    sb = 0.98078528f * sa + 0.19509032f * ca;
                }
                const float cp = C4 * (cb - sb);
                const float sp = C4 * (cb + sb);
                float2 Xk, Xc;
                unpack_pair(Z1[h][0], Z2[h][3], cb, sb, Xk, Xc);
                row[ue] = Xk; row[1024 - ue] = Xc;
                unpack_pair(Z1[h][1], Z2[h][2], cp, sp, Xk, Xc);
                row[ue + 256] = Xk; row[768 - ue] = Xc;
                unpack_pair(Z1[h][2], Z2[h][1], -sb, cb, Xk, Xc);
                row[ue + 512] = Xk; row[512 - ue] = Xc;
                unpack_pair(Z1[h][3], Z2[h][0], -sp, cp, Xk, Xc);
                row[ue + 768] = Xk; row[256 - ue] = Xc;
            }
        }
    }
    __syncthreads();

    // ---- transposed store: lane j -> frame j&7, bin j>>3 (+64/iter) ----
    const int  fs     = tid & 7;
    const int  kb     = tid >> 3;
    const int  fstore = g * FPB + fs;
    const bool valid  = (fstore < NFRAMES);
    const long ro       = ((long)b * NBINS) * NFRAMES + fstore;
    const long imag_off = (long)NB * NBINS * NFRAMES;
    const float2* __restrict__ Xrow = buf + fs * SROW;
#pragma unroll
    for (int i = 0; i < 17; i++) {
        const int k = kb + (i << 6);
        if (k <= NC && valid) {
            const float2 X = Xrow[k];
            const long o = ro + (long)k * NFRAMES;
            out[o]            = X.x;
            out[imag_off + o] = X.y;
        }
    }
}

extern "C" void kernel_launch(void* const* d_in, const int* in_sizes, int n_in,
                              void* d_out, int out_size) {
    const float* x   = (const float*)d_in[0];
    const float* win = (const float*)d_in[1];
    float* out = (float*)d_out;
    const int smem_bytes = FPB * SROW * (int)sizeof(float2);
    cudaFuncSetAttribute(stft_kernel, cudaFuncAttributeMaxDynamicSharedMemorySize,
                         smem_bytes);
    stft_kernel<<<NB * NGRP, THREADS, smem_bytes>>>(x, win, out);
}